// round 9
// baseline (speedup 1.0000x reference)
#include <cuda_runtime.h>
#include <cuda_bf16.h>
#include <cstdint>
#include <cstddef>

#define MTOT 8192
#define KTOT 4096
#define NTOT 4096
#define TM   128
#define TN   128
#define KC   64
#define NITER (KTOT / KC)     // 64
#define STAGES 3
#define STAGE_BYTES ((TM + TN) * KC * 2)      // 32768
#define SMEM_TOTAL  (STAGES * STAGE_BYTES)    // 98304

// scratch (allocation-free): bf16 dequantized operands
__device__ __align__(16) __nv_bfloat16 g_A[(size_t)MTOT * KTOT];
__device__ __align__(16) __nv_bfloat16 g_B[(size_t)NTOT * KTOT];

#define SWZ(o) ((uint32_t)(o) ^ ((((uint32_t)(o)) >> 3) & 0x70u))

static __device__ __forceinline__ uint32_t smem_u32(const void* p) {
    uint32_t a;
    asm("{ .reg .u64 t; cvta.to.shared.u64 t, %1; cvt.u32.u64 %0, t; }" : "=r"(a) : "l"(p));
    return a;
}
static __device__ __forceinline__ void cp16(uint32_t dst, const void* src) {
    asm volatile("cp.async.cg.shared.global [%0], [%1], 16;" :: "r"(dst), "l"(src) : "memory");
}
static __device__ __forceinline__ void cp_commit() {
    asm volatile("cp.async.commit_group;" ::: "memory");
}
static __device__ __forceinline__ void cp_wait1() {
    asm volatile("cp.async.wait_group 1;" ::: "memory");
}
static __device__ __forceinline__ void ldsm4(uint32_t* r, uint32_t a) {
    asm volatile("ldmatrix.sync.aligned.m8n8.x4.shared.b16 {%0,%1,%2,%3}, [%4];"
                 : "=r"(r[0]), "=r"(r[1]), "=r"(r[2]), "=r"(r[3]) : "r"(a));
}
static __device__ __forceinline__ void mma16816(float* d, const uint32_t* a,
                                                uint32_t b0, uint32_t b1) {
    asm volatile(
        "mma.sync.aligned.m16n8k16.row.col.f32.bf16.bf16.f32 "
        "{%0,%1,%2,%3}, {%4,%5,%6,%7}, {%8,%9}, {%0,%1,%2,%3};"
        : "+f"(d[0]), "+f"(d[1]), "+f"(d[2]), "+f"(d[3])
        : "r"(a[0]), "r"(a[1]), "r"(a[2]), "r"(a[3]), "r"(b0), "r"(b1));
}

static __device__ __forceinline__ float e4m3_val(int i) {
    int e = i >> 3, m = i & 7;
    if (e == 0) return (float)m * 0x1p-9f;
    return (float)(8 + m) * __int_as_float((117 + e) << 23);
}

__constant__ float FP4_TAB[16] = {0.0f, 0.5f, 1.0f, 1.5f, 2.0f, 3.0f, 4.0f, 6.0f,
                                  -0.0f, -0.5f, -1.0f, -1.5f, -2.0f, -3.0f, -4.0f, -6.0f};

// ============ kernel 1: activation quant -> g_A = fp4_level * e4m3_bscale (bf16, exact)
__global__ void __launch_bounds__(256) quant_kernel(const float* __restrict__ x,
                                                    const float* __restrict__ in_scale) {
    const int g = blockIdx.x * 256 + threadIdx.x;         // m*256 + group
    const float s = __ldg(in_scale);
    const float4* px = reinterpret_cast<const float4*>(x) + (size_t)g * 4;
    float4 v0 = px[0], v1 = px[1], v2 = px[2], v3 = px[3];
    float xv[16] = {v0.x, v0.y, v0.z, v0.w, v1.x, v1.y, v1.z, v1.w,
                    v2.x, v2.y, v2.z, v2.w, v3.x, v3.y, v3.z, v3.w};
    float amax = 0.0f;
#pragma unroll
    for (int i = 0; i < 16; ++i) amax = fmaxf(amax, fabsf(xv[i]));

    float v = fminf(amax / (6.0f * s), 448.0f);           // exact fp32 division
    int lo = 0, hi = 127;                                 // searchsorted-left over e4m3 table
    while (lo < hi) { int mid = (lo + hi) >> 1; if (e4m3_val(mid) < v) lo = mid + 1; else hi = mid; }
    int idx = lo < 1 ? 1 : (lo > 126 ? 126 : lo);
    float ta = e4m3_val(idx - 1), tb = e4m3_val(idx);
    float bs = ((v - ta) <= (tb - v)) ? ta : tb;          // ties -> lower, as reference

    float eff = bs * s;
    float safe = (eff > 0.0f) ? eff : 1.0f;
    float rcp = 1.0f / safe, nsafe = -safe;

    uint32_t ow[8];
#pragma unroll
    for (int j = 0; j < 8; ++j) {
        unsigned short hw[2];
#pragma unroll
        for (int u = 0; u < 2; ++u) {
            float a0 = xv[2 * j + u];
            float q0 = a0 * rcp;                          // Markstein: RN(a0/safe)
            float rr = fmaf(nsafe, q0, a0);
            float qq = fmaf(rr, rcp, q0);
            float aa = fabsf(qq);
            float lev = 0.0f;                             // fp4 RN, ties away from zero
            lev = aa >= 0.25f ? 0.5f : lev;
            lev = aa >= 0.75f ? 1.0f : lev;
            lev = aa >= 1.25f ? 1.5f : lev;
            lev = aa >= 1.75f ? 2.0f : lev;
            lev = aa >= 2.5f  ? 3.0f : lev;
            lev = aa >= 3.5f  ? 4.0f : lev;
            lev = aa >= 5.0f  ? 6.0f : lev;
            hw[u] = __bfloat16_as_ushort(__float2bfloat16_rn(copysignf(lev * bs, qq)));
        }
        ow[j] = (uint32_t)hw[0] | ((uint32_t)hw[1] << 16);
    }
    uint4* dst = reinterpret_cast<uint4*>(g_A + (size_t)g * 16);
    dst[0] = make_uint4(ow[0], ow[1], ow[2], ow[3]);
    dst[1] = make_uint4(ow[4], ow[5], ow[6], ow[7]);
}

// ============ kernel 2: weight dequant -> g_B = fp4 * e4m3_scale (bf16, exact)
__global__ void __launch_bounds__(256) wdq_kernel(const int* __restrict__ w,
                                                  const int* __restrict__ ws) {
    const int g = blockIdx.x * 256 + threadIdx.x;         // n*256 + group
    const int bits = __ldg(ws + g);
    const int e = (bits >> 3) & 15, mm = bits & 7;
    float mag = e ? (float)(8 + mm) * __int_as_float((117 + e) << 23) : (float)mm * 0x1p-9f;
    float sc = (bits & 128) ? -mag : mag;

    const int4* pw = reinterpret_cast<const int4*>(w) + (size_t)g * 2;
    int4 w0 = pw[0], w1 = pw[1];
    int b[8] = {w0.x, w0.y, w0.z, w0.w, w1.x, w1.y, w1.z, w1.w};
    uint32_t ow[8];
#pragma unroll
    for (int j = 0; j < 8; ++j) {
        unsigned short h0 = __bfloat16_as_ushort(__float2bfloat16_rn(FP4_TAB[b[j] & 15] * sc));
        unsigned short h1 = __bfloat16_as_ushort(__float2bfloat16_rn(FP4_TAB[(b[j] >> 4) & 15] * sc));
        ow[j] = (uint32_t)h0 | ((uint32_t)h1 << 16);
    }
    uint4* dst = reinterpret_cast<uint4*>(g_B + (size_t)g * 16);
    dst[0] = make_uint4(ow[0], ow[1], ow[2], ow[3]);
    dst[1] = make_uint4(ow[4], ow[5], ow[6], ow[7]);
}

// ============ kernel 3: mma.sync bf16 GEMM 128x128, KC=64, 3-stage cp.async pipeline
static __device__ __forceinline__ void load_stage(uint32_t sbase, int m0, int n0,
                                                  int it, int tid) {
    const __nv_bfloat16* Ag = g_A + ((size_t)m0 * KTOT + it * KC);
    const __nv_bfloat16* Bg = g_B + ((size_t)n0 * KTOT + it * KC);
#pragma unroll
    for (int t = 0; t < 4; ++t) {                 // A: 128 rows x 8 x 16B
        int i = tid + t * 256, r = i >> 3, c = i & 7;
        cp16(sbase + SWZ(r * 128 + c * 16), Ag + (size_t)r * KTOT + c * 8);
    }
#pragma unroll
    for (int t = 0; t < 4; ++t) {                 // B: 128 rows x 8 x 16B
        int i = tid + t * 256, r = i >> 3, c = i & 7;
        cp16(sbase + 16384u + SWZ(r * 128 + c * 16), Bg + (size_t)r * KTOT + c * 8);
    }
}

__global__ void __launch_bounds__(256, 1) gemm_kernel(const float* __restrict__ in_scale,
                                                      const float* __restrict__ ws2,
                                                      float* __restrict__ out) {
    extern __shared__ char smem[];
    const uint32_t sb = smem_u32(smem);
    const int tid = threadIdx.x;
    const int wid = tid >> 5, lid = tid & 31;
    const int m0 = blockIdx.y * TM;
    const int n0 = blockIdx.x * TN;

    const int m_off = (wid & 1) * 64;             // warp tile: 64(M) x 32(N)
    const int n_off = (wid >> 1) * 32;
    const int lrow = lid & 15;
    const int lhi16 = (lid >> 4) * 16;

    float d[4][4][4];
#pragma unroll
    for (int a = 0; a < 4; ++a)
#pragma unroll
        for (int b = 0; b < 4; ++b)
#pragma unroll
            for (int c = 0; c < 4; ++c) d[a][b][c] = 0.0f;

    // prologue: stages 0,1
    load_stage(sb + 0 * STAGE_BYTES, m0, n0, 0, tid); cp_commit();
    load_stage(sb + 1 * STAGE_BYTES, m0, n0, 1, tid); cp_commit();

    for (int it = 0; it < NITER; ++it) {
        cp_wait1();
        __syncthreads();

        if (it + 2 < NITER)
            load_stage(sb + ((it + 2) % STAGES) * STAGE_BYTES, m0, n0, it + 2, tid);
        cp_commit();

        const uint32_t sA = sb + (it % STAGES) * STAGE_BYTES;
        const uint32_t sB = sA + 16384u;
#pragma unroll
        for (int ks = 0; ks < 4; ++ks) {
            uint32_t afr[4][4], bfr[2][4];
#pragma unroll
            for (int mi = 0; mi < 4; ++mi) {
                uint32_t off = (uint32_t)(m_off + mi * 16 + lrow) * 128 + ks * 32 + lhi16;
                ldsm4(afr[mi], sA + SWZ(off));
            }
#pragma unroll
            for (int ni = 0; ni < 2; ++ni) {
                uint32_t off = (uint32_t)(n_off + ni * 16 + lrow) * 128 + ks * 32 + lhi16;
                ldsm4(bfr[ni], sB + SWZ(off));
            }
#pragma unroll
            for (int mi = 0; mi < 4; ++mi)
#pragma unroll
                for (int j = 0; j < 4; ++j) {
                    const int ni = j >> 1, p = j & 1;
                    mma16816(d[mi][j], afr[mi], bfr[ni][p], bfr[ni][p + 2]);
                }
        }
    }

    // epilogue: fp32 out * alpha
    const float alpha = __ldg(in_scale) * __ldg(ws2);
    const int qrow = lid >> 2, qcol = (lid & 3) * 2;
#pragma unroll
    for (int mi = 0; mi < 4; ++mi) {
#pragma unroll
        for (int j = 0; j < 4; ++j) {
            const int row = m0 + m_off + mi * 16 + qrow;
            const int col = n0 + n_off + j * 8 + qcol;
            float2 v0 = make_float2(d[mi][j][0] * alpha, d[mi][j][1] * alpha);
            float2 v1 = make_float2(d[mi][j][2] * alpha, d[mi][j][3] * alpha);
            *reinterpret_cast<float2*>(out + (size_t)row * NTOT + col) = v0;
            *reinterpret_cast<float2*>(out + (size_t)(row + 8) * NTOT + col) = v1;
        }
    }
}

// ---------------- launch ----------------
extern "C" void kernel_launch(void* const* d_in, const int* in_sizes, int n_in,
                              void* d_out, int out_size) {
    const float* x        = (const float*)d_in[0];
    const int*   weight   = (const int*)d_in[1];
    const int*   wscale   = (const int*)d_in[2];
    const float* wscale2  = (const float*)d_in[3];
    const float* in_scale = (const float*)d_in[4];
    float* out = (float*)d_out;

    cudaFuncSetAttribute(gemm_kernel, cudaFuncAttributeMaxDynamicSharedMemorySize, SMEM_TOTAL);

    quant_kernel<<<(MTOT * (KTOT / 16)) / 256, 256>>>(x, in_scale);
    wdq_kernel<<<(NTOT * (KTOT / 16)) / 256, 256>>>(weight, wscale);
    dim3 grid(NTOT / TN, MTOT / TM);
    gemm_kernel<<<grid, 256, SMEM_TOTAL>>>(in_scale, wscale2, out);
}

// round 10
// speedup vs baseline: 1.1543x; 1.1543x over previous
#include <cuda_runtime.h>
#include <cuda_bf16.h>
#include <cstdint>
#include <cstddef>

#define MTOT 8192
#define KTOT 4096
#define NTOT 4096
#define TM   128
#define TN   256
#define KC   64
#define NITER (KTOT / KC)     // 64
#define STAGES 3
#define A_BYTES (TM * KC * 2)                  // 16384
#define STAGE_BYTES ((TM + TN) * KC * 2)       // 49152
#define SMEM_TOTAL  (STAGES * STAGE_BYTES)     // 147456

// scratch (allocation-free): bf16 dequantized operands
__device__ __align__(16) __nv_bfloat16 g_A[(size_t)MTOT * KTOT];
__device__ __align__(16) __nv_bfloat16 g_B[(size_t)NTOT * KTOT];

#define SWZ(o) ((uint32_t)(o) ^ ((((uint32_t)(o)) >> 3) & 0x70u))

static __device__ __forceinline__ uint32_t smem_u32(const void* p) {
    uint32_t a;
    asm("{ .reg .u64 t; cvta.to.shared.u64 t, %1; cvt.u32.u64 %0, t; }" : "=r"(a) : "l"(p));
    return a;
}
static __device__ __forceinline__ void cp16(uint32_t dst, const void* src) {
    asm volatile("cp.async.cg.shared.global [%0], [%1], 16;" :: "r"(dst), "l"(src) : "memory");
}
static __device__ __forceinline__ void cp_commit() {
    asm volatile("cp.async.commit_group;" ::: "memory");
}
static __device__ __forceinline__ void cp_wait1() {
    asm volatile("cp.async.wait_group 1;" ::: "memory");
}
static __device__ __forceinline__ void ldsm4(uint32_t* r, uint32_t a) {
    asm volatile("ldmatrix.sync.aligned.m8n8.x4.shared.b16 {%0,%1,%2,%3}, [%4];"
                 : "=r"(r[0]), "=r"(r[1]), "=r"(r[2]), "=r"(r[3]) : "r"(a));
}
static __device__ __forceinline__ void mma16816(float* d, const uint32_t* a,
                                                uint32_t b0, uint32_t b1) {
    asm volatile(
        "mma.sync.aligned.m16n8k16.row.col.f32.bf16.bf16.f32 "
        "{%0,%1,%2,%3}, {%4,%5,%6,%7}, {%8,%9}, {%0,%1,%2,%3};"
        : "+f"(d[0]), "+f"(d[1]), "+f"(d[2]), "+f"(d[3])
        : "r"(a[0]), "r"(a[1]), "r"(a[2]), "r"(a[3]), "r"(b0), "r"(b1));
}

static __device__ __forceinline__ float e4m3_val(int i) {
    int e = i >> 3, m = i & 7;
    if (e == 0) return (float)m * 0x1p-9f;
    return (float)(8 + m) * __int_as_float((117 + e) << 23);
}

__constant__ float FP4_TAB[16] = {0.0f, 0.5f, 1.0f, 1.5f, 2.0f, 3.0f, 4.0f, 6.0f,
                                  -0.0f, -0.5f, -1.0f, -1.5f, -2.0f, -3.0f, -4.0f, -6.0f};

// ============ kernel 1: activation quant -> g_A = fp4_level * e4m3_bscale (bf16, exact)
__global__ void __launch_bounds__(256) quant_kernel(const float* __restrict__ x,
                                                    const float* __restrict__ in_scale) {
    const int g = blockIdx.x * 256 + threadIdx.x;         // m*256 + group
    const float s = __ldg(in_scale);
    const float4* px = reinterpret_cast<const float4*>(x) + (size_t)g * 4;
    float4 v0 = px[0], v1 = px[1], v2 = px[2], v3 = px[3];
    float xv[16] = {v0.x, v0.y, v0.z, v0.w, v1.x, v1.y, v1.z, v1.w,
                    v2.x, v2.y, v2.z, v2.w, v3.x, v3.y, v3.z, v3.w};
    float amax = 0.0f;
#pragma unroll
    for (int i = 0; i < 16; ++i) amax = fmaxf(amax, fabsf(xv[i]));

    float v = fminf(amax / (6.0f * s), 448.0f);           // exact fp32 division
    int lo = 0, hi = 127;                                 // searchsorted-left over e4m3 table
    while (lo < hi) { int mid = (lo + hi) >> 1; if (e4m3_val(mid) < v) lo = mid + 1; else hi = mid; }
    int idx = lo < 1 ? 1 : (lo > 126 ? 126 : lo);
    float ta = e4m3_val(idx - 1), tb = e4m3_val(idx);
    float bs = ((v - ta) <= (tb - v)) ? ta : tb;          // ties -> lower, as reference

    float eff = bs * s;
    float safe = (eff > 0.0f) ? eff : 1.0f;
    float rcp = 1.0f / safe, nsafe = -safe;

    uint32_t ow[8];
#pragma unroll
    for (int j = 0; j < 8; ++j) {
        unsigned short hw[2];
#pragma unroll
        for (int u = 0; u < 2; ++u) {
            float a0 = xv[2 * j + u];
            float q0 = a0 * rcp;                          // Markstein: RN(a0/safe)
            float rr = fmaf(nsafe, q0, a0);
            float qq = fmaf(rr, rcp, q0);
            float aa = fabsf(qq);
            float lev = 0.0f;                             // fp4 RN, ties away from zero
            lev = aa >= 0.25f ? 0.5f : lev;
            lev = aa >= 0.75f ? 1.0f : lev;
            lev = aa >= 1.25f ? 1.5f : lev;
            lev = aa >= 1.75f ? 2.0f : lev;
            lev = aa >= 2.5f  ? 3.0f : lev;
            lev = aa >= 3.5f  ? 4.0f : lev;
            lev = aa >= 5.0f  ? 6.0f : lev;
            hw[u] = __bfloat16_as_ushort(__float2bfloat16_rn(copysignf(lev * bs, qq)));
        }
        ow[j] = (uint32_t)hw[0] | ((uint32_t)hw[1] << 16);
    }
    uint4* dst = reinterpret_cast<uint4*>(g_A + (size_t)g * 16);
    dst[0] = make_uint4(ow[0], ow[1], ow[2], ow[3]);
    dst[1] = make_uint4(ow[4], ow[5], ow[6], ow[7]);
}

// ============ kernel 2: weight dequant -> g_B = fp4 * e4m3_scale (bf16, exact)
__global__ void __launch_bounds__(256) wdq_kernel(const int* __restrict__ w,
                                                  const int* __restrict__ ws) {
    const int g = blockIdx.x * 256 + threadIdx.x;         // n*256 + group
    const int bits = __ldg(ws + g);
    const int e = (bits >> 3) & 15, mm = bits & 7;
    float mag = e ? (float)(8 + mm) * __int_as_float((117 + e) << 23) : (float)mm * 0x1p-9f;
    float sc = (bits & 128) ? -mag : mag;

    const int4* pw = reinterpret_cast<const int4*>(w) + (size_t)g * 2;
    int4 w0 = pw[0], w1 = pw[1];
    int b[8] = {w0.x, w0.y, w0.z, w0.w, w1.x, w1.y, w1.z, w1.w};
    uint32_t ow[8];
#pragma unroll
    for (int j = 0; j < 8; ++j) {
        unsigned short h0 = __bfloat16_as_ushort(__float2bfloat16_rn(FP4_TAB[b[j] & 15] * sc));
        unsigned short h1 = __bfloat16_as_ushort(__float2bfloat16_rn(FP4_TAB[(b[j] >> 4) & 15] * sc));
        ow[j] = (uint32_t)h0 | ((uint32_t)h1 << 16);
    }
    uint4* dst = reinterpret_cast<uint4*>(g_B + (size_t)g * 16);
    dst[0] = make_uint4(ow[0], ow[1], ow[2], ow[3]);
    dst[1] = make_uint4(ow[4], ow[5], ow[6], ow[7]);
}

// ============ kernel 3: mma.sync bf16 GEMM 128x256, KC=64, 3-stage cp.async, 512 thr
static __device__ __forceinline__ void load_stage(uint32_t sbase, int m0, int n0,
                                                  int it, int tid) {
    const __nv_bfloat16* Ag = g_A + ((size_t)m0 * KTOT + it * KC);
    const __nv_bfloat16* Bg = g_B + ((size_t)n0 * KTOT + it * KC);
#pragma unroll
    for (int t = 0; t < 2; ++t) {                 // A: 128 rows x 8 x 16B = 1024 chunks
        int i = tid + t * 512, r = i >> 3, c = i & 7;
        cp16(sbase + SWZ(r * 128 + c * 16), Ag + (size_t)r * KTOT + c * 8);
    }
#pragma unroll
    for (int t = 0; t < 4; ++t) {                 // B: 256 rows x 8 x 16B = 2048 chunks
        int i = tid + t * 512, r = i >> 3, c = i & 7;
        cp16(sbase + A_BYTES + SWZ(r * 128 + c * 16), Bg + (size_t)r * KTOT + c * 8);
    }
}

__global__ void __launch_bounds__(512, 1) gemm_kernel(const float* __restrict__ in_scale,
                                                      const float* __restrict__ ws2,
                                                      float* __restrict__ out) {
    extern __shared__ char smem[];
    const uint32_t sb = smem_u32(smem);
    const int tid = threadIdx.x;
    const int wid = tid >> 5, lid = tid & 31;
    const int m0 = blockIdx.y * TM;
    const int n0 = blockIdx.x * TN;

    const int m_off = (wid & 3) * 32;             // 4 M-warps x 4 N-warps, warp tile 32x64
    const int n_off = (wid >> 2) * 64;
    const int lrow = lid & 15;
    const int lhi16 = (lid >> 4) * 16;

    float d[2][8][4];
#pragma unroll
    for (int a = 0; a < 2; ++a)
#pragma unroll
        for (int b = 0; b < 8; ++b)
#pragma unroll
            for (int c = 0; c < 4; ++c) d[a][b][c] = 0.0f;

    // prologue: stages 0,1
    load_stage(sb + 0 * STAGE_BYTES, m0, n0, 0, tid); cp_commit();
    load_stage(sb + 1 * STAGE_BYTES, m0, n0, 1, tid); cp_commit();

    for (int it = 0; it < NITER; ++it) {
        cp_wait1();
        __syncthreads();

        if (it + 2 < NITER)
            load_stage(sb + ((it + 2) % STAGES) * STAGE_BYTES, m0, n0, it + 2, tid);
        cp_commit();

        const uint32_t sA = sb + (it % STAGES) * STAGE_BYTES;
        const uint32_t sB = sA + A_BYTES;
#pragma unroll
        for (int ks = 0; ks < 4; ++ks) {
            uint32_t afr[2][4], bfr[4][4];
#pragma unroll
            for (int mi = 0; mi < 2; ++mi) {
                uint32_t off = (uint32_t)(m_off + mi * 16 + lrow) * 128 + ks * 32 + lhi16;
                ldsm4(afr[mi], sA + SWZ(off));
            }
#pragma unroll
            for (int ni = 0; ni < 4; ++ni) {
                uint32_t off = (uint32_t)(n_off + ni * 16 + lrow) * 128 + ks * 32 + lhi16;
                ldsm4(bfr[ni], sB + SWZ(off));
            }
#pragma unroll
            for (int mi = 0; mi < 2; ++mi)
#pragma unroll
                for (int j = 0; j < 8; ++j) {
                    const int ni = j >> 1, p = j & 1;
                    mma16816(d[mi][j], afr[mi], bfr[ni][p], bfr[ni][p + 2]);
                }
        }
    }

    // epilogue: fp32 out * alpha
    const float alpha = __ldg(in_scale) * __ldg(ws2);
    const int qrow = lid >> 2, qcol = (lid & 3) * 2;
#pragma unroll
    for (int mi = 0; mi < 2; ++mi) {
#pragma unroll
        for (int j = 0; j < 8; ++j) {
            const int row = m0 + m_off + mi * 16 + qrow;
            const int col = n0 + n_off + j * 8 + qcol;
            float2 v0 = make_float2(d[mi][j][0] * alpha, d[mi][j][1] * alpha);
            float2 v1 = make_float2(d[mi][j][2] * alpha, d[mi][j][3] * alpha);
            *reinterpret_cast<float2*>(out + (size_t)row * NTOT + col) = v0;
            *reinterpret_cast<float2*>(out + (size_t)(row + 8) * NTOT + col) = v1;
        }
    }
}

// ---------------- launch ----------------
extern "C" void kernel_launch(void* const* d_in, const int* in_sizes, int n_in,
                              void* d_out, int out_size) {
    const float* x        = (const float*)d_in[0];
    const int*   weight   = (const int*)d_in[1];
    const int*   wscale   = (const int*)d_in[2];
    const float* wscale2  = (const float*)d_in[3];
    const float* in_scale = (const float*)d_in[4];
    float* out = (float*)d_out;

    cudaFuncSetAttribute(gemm_kernel, cudaFuncAttributeMaxDynamicSharedMemorySize, SMEM_TOTAL);

    quant_kernel<<<(MTOT * (KTOT / 16)) / 256, 256>>>(x, in_scale);
    wdq_kernel<<<(NTOT * (KTOT / 16)) / 256, 256>>>(weight, wscale);
    dim3 grid(NTOT / TN, MTOT / TM);
    gemm_kernel<<<grid, 512, SMEM_TOTAL>>>(in_scale, wscale2, out);
}

// round 11
// speedup vs baseline: 1.1822x; 1.0241x over previous
#include <cuda_runtime.h>
#include <cuda_bf16.h>
#include <cstdint>
#include <cstddef>

#define MTOT 8192
#define KTOT 4096
#define NTOT 4096
#define TM   128
#define TN   256
#define KC   128
#define NITER (KTOT / KC)                      // 32
#define A_STAGE_BYTES (TM * KC * 2)            // 32768
#define STAGE_BYTES ((TM + TN) * KC * 2)       // 98304
#define SMEM_TOTAL  (2 * STAGE_BYTES)          // 196608

// scratch (allocation-free): bf16 dequantized operands
__device__ __align__(16) __nv_bfloat16 g_A[(size_t)MTOT * KTOT];
__device__ __align__(16) __nv_bfloat16 g_B[(size_t)NTOT * KTOT];

#define SWZ(o) ((uint32_t)(o) ^ ((((uint32_t)(o)) >> 3) & 0x70u))

static __device__ __forceinline__ uint32_t smem_u32(const void* p) {
    uint32_t a;
    asm("{ .reg .u64 t; cvta.to.shared.u64 t, %1; cvt.u32.u64 %0, t; }" : "=r"(a) : "l"(p));
    return a;
}
static __device__ __forceinline__ void cp16(uint32_t dst, const void* src) {
    asm volatile("cp.async.cg.shared.global [%0], [%1], 16;" :: "r"(dst), "l"(src) : "memory");
}
static __device__ __forceinline__ void cp_commit() {
    asm volatile("cp.async.commit_group;" ::: "memory");
}
static __device__ __forceinline__ void cp_wait0() {
    asm volatile("cp.async.wait_group 0;" ::: "memory");
}
static __device__ __forceinline__ void ldsm4(uint32_t* r, uint32_t a) {
    asm volatile("ldmatrix.sync.aligned.m8n8.x4.shared.b16 {%0,%1,%2,%3}, [%4];"
                 : "=r"(r[0]), "=r"(r[1]), "=r"(r[2]), "=r"(r[3]) : "r"(a));
}
static __device__ __forceinline__ void mma16816(float* d, const uint32_t* a,
                                                uint32_t b0, uint32_t b1) {
    asm volatile(
        "mma.sync.aligned.m16n8k16.row.col.f32.bf16.bf16.f32 "
        "{%0,%1,%2,%3}, {%4,%5,%6,%7}, {%8,%9}, {%0,%1,%2,%3};"
        : "+f"(d[0]), "+f"(d[1]), "+f"(d[2]), "+f"(d[3])
        : "r"(a[0]), "r"(a[1]), "r"(a[2]), "r"(a[3]), "r"(b0), "r"(b1));
}

static __device__ __forceinline__ float e4m3_val(int i) {
    int e = i >> 3, m = i & 7;
    if (e == 0) return (float)m * 0x1p-9f;
    return (float)(8 + m) * __int_as_float((117 + e) << 23);
}

__constant__ float FP4_TAB[16] = {0.0f, 0.5f, 1.0f, 1.5f, 2.0f, 3.0f, 4.0f, 6.0f,
                                  -0.0f, -0.5f, -1.0f, -1.5f, -2.0f, -3.0f, -4.0f, -6.0f};

// ============ fused prep: blocks [0,8192) = activation quant, [8192,12288) = weight dequant
__global__ void __launch_bounds__(256) prep_kernel(const float* __restrict__ x,
                                                   const float* __restrict__ in_scale,
                                                   const int* __restrict__ w,
                                                   const int* __restrict__ ws) {
    if (blockIdx.x < 8192) {
        // ---- activation quant -> g_A = fp4_level * e4m3_bscale (bf16, exact) ----
        const int g = blockIdx.x * 256 + threadIdx.x;     // m*256 + group
        const float s = __ldg(in_scale);
        const float4* px = reinterpret_cast<const float4*>(x) + (size_t)g * 4;
        float4 v0 = px[0], v1 = px[1], v2 = px[2], v3 = px[3];
        float xv[16] = {v0.x, v0.y, v0.z, v0.w, v1.x, v1.y, v1.z, v1.w,
                        v2.x, v2.y, v2.z, v2.w, v3.x, v3.y, v3.z, v3.w};
        float amax = 0.0f;
#pragma unroll
        for (int i = 0; i < 16; ++i) amax = fmaxf(amax, fabsf(xv[i]));

        float v = fminf(amax / (6.0f * s), 448.0f);       // exact fp32 division
        int lo = 0, hi = 127;                             // searchsorted-left over e4m3 table
        while (lo < hi) { int mid = (lo + hi) >> 1; if (e4m3_val(mid) < v) lo = mid + 1; else hi = mid; }
        int idx = lo < 1 ? 1 : (lo > 126 ? 126 : lo);
        float ta = e4m3_val(idx - 1), tb = e4m3_val(idx);
        float bs = ((v - ta) <= (tb - v)) ? ta : tb;      // ties -> lower, as reference

        float eff = bs * s;
        float safe = (eff > 0.0f) ? eff : 1.0f;
        float rcp = 1.0f / safe, nsafe = -safe;

        uint32_t ow[8];
#pragma unroll
        for (int j = 0; j < 8; ++j) {
            unsigned short hw[2];
#pragma unroll
            for (int u = 0; u < 2; ++u) {
                float a0 = xv[2 * j + u];
                float q0 = a0 * rcp;                      // Markstein: RN(a0/safe)
                float rr = fmaf(nsafe, q0, a0);
                float qq = fmaf(rr, rcp, q0);
                float aa = fabsf(qq);
                float lev = 0.0f;                         // fp4 RN, ties away from zero
                lev = aa >= 0.25f ? 0.5f : lev;
                lev = aa >= 0.75f ? 1.0f : lev;
                lev = aa >= 1.25f ? 1.5f : lev;
                lev = aa >= 1.75f ? 2.0f : lev;
                lev = aa >= 2.5f  ? 3.0f : lev;
                lev = aa >= 3.5f  ? 4.0f : lev;
                lev = aa >= 5.0f  ? 6.0f : lev;
                hw[u] = __bfloat16_as_ushort(__float2bfloat16_rn(copysignf(lev * bs, qq)));
            }
            ow[j] = (uint32_t)hw[0] | ((uint32_t)hw[1] << 16);
        }
        uint4* dst = reinterpret_cast<uint4*>(g_A + (size_t)g * 16);
        dst[0] = make_uint4(ow[0], ow[1], ow[2], ow[3]);
        dst[1] = make_uint4(ow[4], ow[5], ow[6], ow[7]);
    } else {
        // ---- weight dequant -> g_B = fp4 * e4m3_scale (bf16, exact) ----
        const int g = (blockIdx.x - 8192) * 256 + threadIdx.x;   // n*256 + group
        const int bits = __ldg(ws + g);
        const int e = (bits >> 3) & 15, mm = bits & 7;
        float mag = e ? (float)(8 + mm) * __int_as_float((117 + e) << 23) : (float)mm * 0x1p-9f;
        float sc = (bits & 128) ? -mag : mag;

        const int4* pw = reinterpret_cast<const int4*>(w) + (size_t)g * 2;
        int4 w0 = pw[0], w1 = pw[1];
        int b[8] = {w0.x, w0.y, w0.z, w0.w, w1.x, w1.y, w1.z, w1.w};
        uint32_t ow[8];
#pragma unroll
        for (int j = 0; j < 8; ++j) {
            unsigned short h0 = __bfloat16_as_ushort(__float2bfloat16_rn(FP4_TAB[b[j] & 15] * sc));
            unsigned short h1 = __bfloat16_as_ushort(__float2bfloat16_rn(FP4_TAB[(b[j] >> 4) & 15] * sc));
            ow[j] = (uint32_t)h0 | ((uint32_t)h1 << 16);
        }
        uint4* dst = reinterpret_cast<uint4*>(g_B + (size_t)g * 16);
        dst[0] = make_uint4(ow[0], ow[1], ow[2], ow[3]);
        dst[1] = make_uint4(ow[4], ow[5], ow[6], ow[7]);
    }
}

// ============ GEMM: mma.sync bf16 128x256, KC=128 (2x64 sub-tiles), 2-stage cp.async
// stage layout: A sub0 @0 (16K) | A sub1 @16K | B sub0 @32K (32K) | B sub1 @64K
static __device__ __forceinline__ void load_stage(uint32_t sbase, int m0, int n0,
                                                  int it, int tid) {
    const __nv_bfloat16* Ag = g_A + ((size_t)m0 * KTOT + it * KC);
    const __nv_bfloat16* Bg = g_B + ((size_t)n0 * KTOT + it * KC);
#pragma unroll
    for (int t = 0; t < 4; ++t) {                 // A: 2 subs x 128 rows x 8 x 16B
        int i = tid + t * 512;
        int sub = i >> 10, r = (i >> 3) & 127, c = i & 7;
        cp16(sbase + (uint32_t)sub * 16384u + SWZ(r * 128 + c * 16),
             Ag + (size_t)r * KTOT + sub * 64 + c * 8);
    }
#pragma unroll
    for (int t = 0; t < 8; ++t) {                 // B: 2 subs x 256 rows x 8 x 16B
        int i = tid + t * 512;
        int sub = i >> 11, r = (i >> 3) & 255, c = i & 7;
        cp16(sbase + 32768u + (uint32_t)sub * 32768u + SWZ(r * 128 + c * 16),
             Bg + (size_t)r * KTOT + sub * 64 + c * 8);
    }
}

__global__ void __launch_bounds__(512, 1) gemm_kernel(const float* __restrict__ in_scale,
                                                      const float* __restrict__ ws2,
                                                      float* __restrict__ out) {
    extern __shared__ char smem[];
    const uint32_t sb = smem_u32(smem);
    const int tid = threadIdx.x;
    const int wid = tid >> 5, lid = tid & 31;
    const int m0 = blockIdx.y * TM;
    const int n0 = blockIdx.x * TN;

    const int m_off = (wid & 3) * 32;             // 4 M-warps x 4 N-warps, warp tile 32x64
    const int n_off = (wid >> 2) * 64;
    const int lrow = lid & 15;
    const int lhi16 = (lid >> 4) * 16;

    float d[2][8][4];
#pragma unroll
    for (int a = 0; a < 2; ++a)
#pragma unroll
        for (int b = 0; b < 8; ++b)
#pragma unroll
            for (int c = 0; c < 4; ++c) d[a][b][c] = 0.0f;

    // prologue: stage 0
    load_stage(sb, m0, n0, 0, tid);
    cp_commit();

    for (int it = 0; it < NITER; ++it) {
        cp_wait0();                                // chunk `it` resident
        __syncthreads();                           // visible to all; prev compute done

        if (it + 1 < NITER) {                      // overlap next load with this compute
            load_stage(sb + (uint32_t)((it + 1) & 1) * STAGE_BYTES, m0, n0, it + 1, tid);
            cp_commit();
        }

        const uint32_t sA = sb + (uint32_t)(it & 1) * STAGE_BYTES;
        const uint32_t sB = sA + 32768u;
#pragma unroll
        for (int ks = 0; ks < 8; ++ks) {
            const int sub = ks >> 2, kk = ks & 3;
            const uint32_t aB = sA + (uint32_t)sub * 16384u;
            const uint32_t bB = sB + (uint32_t)sub * 32768u;
            uint32_t afr[2][4], bfr[4][4];
#pragma unroll
            for (int mi = 0; mi < 2; ++mi) {
                uint32_t off = (uint32_t)(m_off + mi * 16 + lrow) * 128 + kk * 32 + lhi16;
                ldsm4(afr[mi], aB + SWZ(off));
            }
#pragma unroll
            for (int ni = 0; ni < 4; ++ni) {
                uint32_t off = (uint32_t)(n_off + ni * 16 + lrow) * 128 + kk * 32 + lhi16;
                ldsm4(bfr[ni], bB + SWZ(off));
            }
#pragma unroll
            for (int mi = 0; mi < 2; ++mi)
#pragma unroll
                for (int j = 0; j < 8; ++j) {
                    const int ni = j >> 1, p = j & 1;
                    mma16816(d[mi][j], afr[mi], bfr[ni][p], bfr[ni][p + 2]);
                }
        }
    }

    // epilogue: fp32 out * alpha
    const float alpha = __ldg(in_scale) * __ldg(ws2);
    const int qrow = lid >> 2, qcol = (lid & 3) * 2;
#pragma unroll
    for (int mi = 0; mi < 2; ++mi) {
#pragma unroll
        for (int j = 0; j < 8; ++j) {
            const int row = m0 + m_off + mi * 16 + qrow;
            const int col = n0 + n_off + j * 8 + qcol;
            float2 v0 = make_float2(d[mi][j][0] * alpha, d[mi][j][1] * alpha);
            float2 v1 = make_float2(d[mi][j][2] * alpha, d[mi][j][3] * alpha);
            *reinterpret_cast<float2*>(out + (size_t)row * NTOT + col) = v0;
            *reinterpret_cast<float2*>(out + (size_t)(row + 8) * NTOT + col) = v1;
        }
    }
}

// ---------------- launch ----------------
extern "C" void kernel_launch(void* const* d_in, const int* in_sizes, int n_in,
                              void* d_out, int out_size) {
    const float* x        = (const float*)d_in[0];
    const int*   weight   = (const int*)d_in[1];
    const int*   wscale   = (const int*)d_in[2];
    const float* wscale2  = (const float*)d_in[3];
    const float* in_scale = (const float*)d_in[4];
    float* out = (float*)d_out;

    cudaFuncSetAttribute(gemm_kernel, cudaFuncAttributeMaxDynamicSharedMemorySize, SMEM_TOTAL);

    prep_kernel<<<12288, 256>>>(x, in_scale, weight, wscale);
    dim3 grid(NTOT / TN, MTOT / TM);
    gemm_kernel<<<grid, 512, SMEM_TOTAL>>>(in_scale, wscale2, out);
}

// round 12
// speedup vs baseline: 1.2294x; 1.0400x over previous
#include <cuda_runtime.h>
#include <cuda_bf16.h>
#include <cstdint>
#include <cstddef>

#define MTOT 8192
#define KTOT 4096
#define NTOT 4096
#define TM   128
#define TN   128
#define KC   64
#define NITER (KTOT / KC)                      // 64
#define A_BYTES (TM * KC * 2)                  // 16384
#define STAGE_BYTES ((TM + TN) * KC * 2)       // 32768
#define SMEM_TOTAL  (2 * STAGE_BYTES)          // 65536 per CTA, 2 CTAs/SM

// scratch (allocation-free): bf16 dequantized operands
__device__ __align__(16) __nv_bfloat16 g_A[(size_t)MTOT * KTOT];
__device__ __align__(16) __nv_bfloat16 g_B[(size_t)NTOT * KTOT];

#define SWZ(o) ((uint32_t)(o) ^ ((((uint32_t)(o)) >> 3) & 0x70u))

static __device__ __forceinline__ uint32_t smem_u32(const void* p) {
    uint32_t a;
    asm("{ .reg .u64 t; cvta.to.shared.u64 t, %1; cvt.u32.u64 %0, t; }" : "=r"(a) : "l"(p));
    return a;
}
static __device__ __forceinline__ void cp16(uint32_t dst, const void* src) {
    asm volatile("cp.async.cg.shared.global [%0], [%1], 16;" :: "r"(dst), "l"(src) : "memory");
}
static __device__ __forceinline__ void cp_commit() {
    asm volatile("cp.async.commit_group;" ::: "memory");
}
static __device__ __forceinline__ void cp_wait0() {
    asm volatile("cp.async.wait_group 0;" ::: "memory");
}
static __device__ __forceinline__ void ldsm4(uint32_t* r, uint32_t a) {
    asm volatile("ldmatrix.sync.aligned.m8n8.x4.shared.b16 {%0,%1,%2,%3}, [%4];"
                 : "=r"(r[0]), "=r"(r[1]), "=r"(r[2]), "=r"(r[3]) : "r"(a));
}
static __device__ __forceinline__ void mma16816(float* d, const uint32_t* a,
                                                uint32_t b0, uint32_t b1) {
    asm volatile(
        "mma.sync.aligned.m16n8k16.row.col.f32.bf16.bf16.f32 "
        "{%0,%1,%2,%3}, {%4,%5,%6,%7}, {%8,%9}, {%0,%1,%2,%3};"
        : "+f"(d[0]), "+f"(d[1]), "+f"(d[2]), "+f"(d[3])
        : "r"(a[0]), "r"(a[1]), "r"(a[2]), "r"(a[3]), "r"(b0), "r"(b1));
}

__constant__ float FP4_TAB[16] = {0.0f, 0.5f, 1.0f, 1.5f, 2.0f, 3.0f, 4.0f, 6.0f,
                                  -0.0f, -0.5f, -1.0f, -1.5f, -2.0f, -3.0f, -4.0f, -6.0f};

// e4m3 round-to-nearest with ties-to-LOWER (matches reference searchsorted + "<=" rule).
// v must be in [0, 448].
static __device__ __forceinline__ float e4m3_round_tdown(float v) {
    if (v >= 0.015625f) {                      // normal range: 3 mantissa bits
        uint32_t u = __float_as_uint(v);
        u += 0x7FFFFu;                         // RN, exact-half rounds DOWN
        u &= ~0xFFFFFu;
        return __uint_as_float(u);
    }
    // subnormal range: multiples of 2^-9, ties down
    return ceilf(v * 512.0f - 0.5f) * 0.001953125f;
}

// ============ fused prep: blocks [0,8192) = activation quant, [8192,12288) = weight dequant
__global__ void __launch_bounds__(256) prep_kernel(const float* __restrict__ x,
                                                   const float* __restrict__ in_scale,
                                                   const int* __restrict__ w,
                                                   const int* __restrict__ ws) {
    if (blockIdx.x < 8192) {
        // ---- activation quant -> g_A = fp4_level * e4m3_bscale (bf16, exact) ----
        const int g = blockIdx.x * 256 + threadIdx.x;     // m*256 + group
        const float s = __ldg(in_scale);
        const float4* px = reinterpret_cast<const float4*>(x) + (size_t)g * 4;
        float4 v0 = px[0], v1 = px[1], v2 = px[2], v3 = px[3];
        float xv[16] = {v0.x, v0.y, v0.z, v0.w, v1.x, v1.y, v1.z, v1.w,
                        v2.x, v2.y, v2.z, v2.w, v3.x, v3.y, v3.z, v3.w};
        float amax = 0.0f;
#pragma unroll
        for (int i = 0; i < 16; ++i) amax = fmaxf(amax, fabsf(xv[i]));

        float v = fminf(amax / (6.0f * s), 448.0f);       // exact fp32 division
        float bs = e4m3_round_tdown(v);

        float eff = bs * s;
        float safe = (eff > 0.0f) ? eff : 1.0f;
        float rcp = 1.0f / safe, nsafe = -safe;

        uint32_t ow[8];
#pragma unroll
        for (int j = 0; j < 8; ++j) {
            unsigned short hw[2];
#pragma unroll
            for (int u = 0; u < 2; ++u) {
                float a0 = xv[2 * j + u];
                float q0 = a0 * rcp;                      // Markstein: RN(a0/safe)
                float rr = fmaf(nsafe, q0, a0);
                float qq = fmaf(rr, rcp, q0);
                float aa = fabsf(qq);
                float lev = 0.0f;                         // fp4 RN, ties away from zero
                lev = aa >= 0.25f ? 0.5f : lev;
                lev = aa >= 0.75f ? 1.0f : lev;
                lev = aa >= 1.25f ? 1.5f : lev;
                lev = aa >= 1.75f ? 2.0f : lev;
                lev = aa >= 2.5f  ? 3.0f : lev;
                lev = aa >= 3.5f  ? 4.0f : lev;
                lev = aa >= 5.0f  ? 6.0f : lev;
                hw[u] = __bfloat16_as_ushort(__float2bfloat16_rn(copysignf(lev * bs, qq)));
            }
            ow[j] = (uint32_t)hw[0] | ((uint32_t)hw[1] << 16);
        }
        uint4* dst = reinterpret_cast<uint4*>(g_A + (size_t)g * 16);
        dst[0] = make_uint4(ow[0], ow[1], ow[2], ow[3]);
        dst[1] = make_uint4(ow[4], ow[5], ow[6], ow[7]);
    } else {
        // ---- weight dequant -> g_B = fp4 * e4m3_scale (bf16, exact) ----
        const int g = (blockIdx.x - 8192) * 256 + threadIdx.x;   // n*256 + group
        const int bits = __ldg(ws + g);
        const int e = (bits >> 3) & 15, mm = bits & 7;
        float mag = e ? (float)(8 + mm) * __int_as_float((117 + e) << 23) : (float)mm * 0x1p-9f;
        float sc = (bits & 128) ? -mag : mag;

        const int4* pw = reinterpret_cast<const int4*>(w) + (size_t)g * 2;
        int4 w0 = pw[0], w1 = pw[1];
        int b[8] = {w0.x, w0.y, w0.z, w0.w, w1.x, w1.y, w1.z, w1.w};
        uint32_t ow[8];
#pragma unroll
        for (int j = 0; j < 8; ++j) {
            unsigned short h0 = __bfloat16_as_ushort(__float2bfloat16_rn(FP4_TAB[b[j] & 15] * sc));
            unsigned short h1 = __bfloat16_as_ushort(__float2bfloat16_rn(FP4_TAB[(b[j] >> 4) & 15] * sc));
            ow[j] = (uint32_t)h0 | ((uint32_t)h1 << 16);
        }
        uint4* dst = reinterpret_cast<uint4*>(g_B + (size_t)g * 16);
        dst[0] = make_uint4(ow[0], ow[1], ow[2], ow[3]);
        dst[1] = make_uint4(ow[4], ow[5], ow[6], ow[7]);
    }
}

// ============ GEMM: mma.sync bf16 128x128 per CTA, KC=64, 2-stage, 2 CTAs/SM
static __device__ __forceinline__ void load_stage(uint32_t sbase, int m0, int n0,
                                                  int it, int tid) {
    const __nv_bfloat16* Ag = g_A + ((size_t)m0 * KTOT + it * KC);
    const __nv_bfloat16* Bg = g_B + ((size_t)n0 * KTOT + it * KC);
#pragma unroll
    for (int t = 0; t < 4; ++t) {                 // A: 128 rows x 8 x 16B
        int i = tid + t * 256, r = i >> 3, c = i & 7;
        cp16(sbase + SWZ(r * 128 + c * 16), Ag + (size_t)r * KTOT + c * 8);
    }
#pragma unroll
    for (int t = 0; t < 4; ++t) {                 // B: 128 rows x 8 x 16B
        int i = tid + t * 256, r = i >> 3, c = i & 7;
        cp16(sbase + A_BYTES + SWZ(r * 128 + c * 16), Bg + (size_t)r * KTOT + c * 8);
    }
}

__global__ void __launch_bounds__(256, 2) gemm_kernel(const float* __restrict__ in_scale,
                                                      const float* __restrict__ ws2,
                                                      float* __restrict__ out) {
    extern __shared__ char smem[];
    const uint32_t sb = smem_u32(smem);
    const int tid = threadIdx.x;
    const int wid = tid >> 5, lid = tid & 31;
    const int m0 = blockIdx.y * TM;
    const int n0 = blockIdx.x * TN;

    const int m_off = (wid & 3) * 32;             // 4 M-warps x 2 N-warps, warp tile 32x64
    const int n_off = (wid >> 2) * 64;
    const int lrow = lid & 15;
    const int lhi16 = (lid >> 4) * 16;

    float d[2][8][4];
#pragma unroll
    for (int a = 0; a < 2; ++a)
#pragma unroll
        for (int b = 0; b < 8; ++b)
#pragma unroll
            for (int c = 0; c < 4; ++c) d[a][b][c] = 0.0f;

    // prologue: stage 0
    load_stage(sb, m0, n0, 0, tid);
    cp_commit();

    for (int it = 0; it < NITER; ++it) {
        cp_wait0();
        __syncthreads();

        if (it + 1 < NITER) {
            load_stage(sb + (uint32_t)((it + 1) & 1) * STAGE_BYTES, m0, n0, it + 1, tid);
            cp_commit();
        }

        const uint32_t sA = sb + (uint32_t)(it & 1) * STAGE_BYTES;
        const uint32_t sB = sA + A_BYTES;
#pragma unroll
        for (int kk = 0; kk < 4; ++kk) {
            uint32_t afr[2][4], bfr[4][4];
#pragma unroll
            for (int mi = 0; mi < 2; ++mi) {
                uint32_t off = (uint32_t)(m_off + mi * 16 + lrow) * 128 + kk * 32 + lhi16;
                ldsm4(afr[mi], sA + SWZ(off));
            }
#pragma unroll
            for (int ni = 0; ni < 4; ++ni) {
                uint32_t off = (uint32_t)(n_off + ni * 16 + lrow) * 128 + kk * 32 + lhi16;
                ldsm4(bfr[ni], sB + SWZ(off));
            }
#pragma unroll
            for (int mi = 0; mi < 2; ++mi)
#pragma unroll
                for (int j = 0; j < 8; ++j) {
                    const int ni = j >> 1, p = j & 1;
                    mma16816(d[mi][j], afr[mi], bfr[ni][p], bfr[ni][p + 2]);
                }
        }
    }

    // epilogue: fp32 out * alpha
    const float alpha = __ldg(in_scale) * __ldg(ws2);
    const int qrow = lid >> 2, qcol = (lid & 3) * 2;
#pragma unroll
    for (int mi = 0; mi < 2; ++mi) {
#pragma unroll
        for (int j = 0; j < 8; ++j) {
            const int row = m0 + m_off + mi * 16 + qrow;
            const int col = n0 + n_off + j * 8 + qcol;
            float2 v0 = make_float2(d[mi][j][0] * alpha, d[mi][j][1] * alpha);
            float2 v1 = make_float2(d[mi][j][2] * alpha, d[mi][j][3] * alpha);
            *reinterpret_cast<float2*>(out + (size_t)row * NTOT + col) = v0;
            *reinterpret_cast<float2*>(out + (size_t)(row + 8) * NTOT + col) = v1;
        }
    }
}

// ---------------- launch ----------------
extern "C" void kernel_launch(void* const* d_in, const int* in_sizes, int n_in,
                              void* d_out, int out_size) {
    const float* x        = (const float*)d_in[0];
    const int*   weight   = (const int*)d_in[1];
    const int*   wscale   = (const int*)d_in[2];
    const float* wscale2  = (const float*)d_in[3];
    const float* in_scale = (const float*)d_in[4];
    float* out = (float*)d_out;

    cudaFuncSetAttribute(gemm_kernel, cudaFuncAttributeMaxDynamicSharedMemorySize, SMEM_TOTAL);

    prep_kernel<<<12288, 256>>>(x, in_scale, weight, wscale);
    dim3 grid(NTOT / TN, MTOT / TM);
    gemm_kernel<<<grid, 256, SMEM_TOTAL>>>(in_scale, wscale2, out);
}